// round 4
// baseline (speedup 1.0000x reference)
#include <cuda_runtime.h>
#include <cuda_bf16.h>

#define C_CLASSES 1000
#define NV4 250            // 1000 floats = 250 float4
#define SMOOTH 0.1f

// device scratch (no allocations allowed)
__device__ float g_A[C_CLASSES * C_CLASSES];   // pre-scaled: beta_t * A[t][j]
__device__ float g_beta[C_CLASSES];            // 0.1 / (1 - A[t][t])
__device__ float g_rowS[C_CLASSES];            // sum_j S[t][j]
__device__ float g_partials[65536];
__device__ float g_stage2[256];

__device__ __forceinline__ float warpMax(float v) {
    #pragma unroll
    for (int o = 16; o; o >>= 1) v = fmaxf(v, __shfl_xor_sync(0xffffffffu, v, o));
    return v;
}
__device__ __forceinline__ float warpSum(float v) {
    #pragma unroll
    for (int o = 16; o; o >>= 1) v += __shfl_xor_sync(0xffffffffu, v, o);
    return v;
}

// ---------------------------------------------------------------------------
// Kernel 1: row softmax of class_avg, fold beta scale into stored A.
// grid = 1000 blocks, 256 threads. Each thread owns one float4 (tid < 250).
// ---------------------------------------------------------------------------
__global__ void softmax_prep_kernel(const float* __restrict__ class_avg) {
    const int t   = blockIdx.x;
    const int tid = threadIdx.x;
    const bool full = (tid < NV4);

    const float4* row = (const float4*)(class_avg + (size_t)t * C_CLASSES);
    float4 v = make_float4(0.f, 0.f, 0.f, 0.f);
    if (full) v = row[tid];

    __shared__ float sred[8];
    __shared__ float sb[4];   // [0]=M, [1]=diag exp, [2]=scale

    // --- block max ---
    float m = full ? fmaxf(fmaxf(v.x, v.y), fmaxf(v.z, v.w)) : -3.402823e38f;
    m = warpMax(m);
    if ((tid & 31) == 0) sred[tid >> 5] = m;
    __syncthreads();
    if (tid == 0) {
        float M = sred[0];
        #pragma unroll
        for (int k = 1; k < 8; k++) M = fmaxf(M, sred[k]);
        sb[0] = M;
    }
    __syncthreads();
    const float M = sb[0];

    // --- exp + sum ---
    float4 e = make_float4(0.f, 0.f, 0.f, 0.f);
    float s = 0.f;
    if (full) {
        e.x = __expf(v.x - M); e.y = __expf(v.y - M);
        e.z = __expf(v.z - M); e.w = __expf(v.w - M);
        s = (e.x + e.y) + (e.z + e.w);
    }
    s = warpSum(s);
    __syncthreads();                 // protect sred reuse
    if ((tid & 31) == 0) sred[tid >> 5] = s;
    // diagonal element exp (column index == row index t); t>>2 <= 249 < 250
    if (tid == (t >> 2)) sb[1] = (&e.x)[t & 3];
    __syncthreads();
    if (tid == 0) {
        float S = 0.f;
        #pragma unroll
        for (int k = 0; k < 8; k++) S += sred[k];
        const float Att   = sb[1] / S;
        const float offm  = 1.0f - Att;            // off-diagonal mass
        const float beta  = SMOOTH / offm;
        g_beta[t] = beta;
        g_rowS[t] = (1.0f - SMOOTH) + SMOOTH * ((float)(C_CLASSES - 2) + Att) / offm;
        sb[2] = beta / S;                          // combined scale for stored row
    }
    __syncthreads();
    const float sc = sb[2];
    if (full) {
        float4 o;
        o.x = e.x * sc; o.y = e.y * sc; o.z = e.z * sc; o.w = e.w * sc;
        ((float4*)(g_A + (size_t)t * C_CLASSES))[tid] = o;
    }
}

// ---------------------------------------------------------------------------
// Kernel 2: per-sample fused log-softmax dot. One block (256 thr) per sample.
// loss_i = lse*rowS[t] - beta[t]*sum(x) + dot(Ascaled[t], x) - 0.8*x[t]
// x streamed with evict-first (__ldcs); A rows left cacheable (L2-resident).
// ---------------------------------------------------------------------------
__global__ void loss_kernel(const float* __restrict__ x,
                            const int* __restrict__ target) {
    const int i   = blockIdx.x;
    const int tid = threadIdx.x;
    const int t   = target[i];
    const bool full = (tid < NV4);

    const float4* xr = (const float4*)(x   + (size_t)i * C_CLASSES);
    const float4* ar = (const float4*)(g_A + (size_t)t * C_CLASSES);

    float4 xv = make_float4(0.f, 0.f, 0.f, 0.f);
    float4 av = make_float4(0.f, 0.f, 0.f, 0.f);
    if (full) { xv = __ldcs(xr + tid); av = __ldg(ar + tid); }

    __shared__ float sred[8];
    __shared__ float s3[8][3];
    __shared__ float sb[2];   // [0]=M, [1]=x_t

    // --- block max of x row ---
    float m = full ? fmaxf(fmaxf(xv.x, xv.y), fmaxf(xv.z, xv.w)) : -3.402823e38f;
    m = warpMax(m);
    if ((tid & 31) == 0) sred[tid >> 5] = m;
    __syncthreads();
    if (tid == 0) {
        float M = sred[0];
        #pragma unroll
        for (int k = 1; k < 8; k++) M = fmaxf(M, sred[k]);
        sb[0] = M;
    }
    if (tid == (t >> 2)) sb[1] = (&xv.x)[t & 3];
    __syncthreads();
    const float M = sb[0];

    // --- fused: exp-sum, plain sum, dot with scaled A row ---
    float es = 0.f, sx = 0.f, dt = 0.f;
    if (full) {
        es = (__expf(xv.x - M) + __expf(xv.y - M)) +
             (__expf(xv.z - M) + __expf(xv.w - M));
        sx = (xv.x + xv.y) + (xv.z + xv.w);
        dt = fmaf(xv.x, av.x, fmaf(xv.y, av.y, fmaf(xv.z, av.z, xv.w * av.w)));
    }
    es = warpSum(es); sx = warpSum(sx); dt = warpSum(dt);
    if ((tid & 31) == 0) {
        const int w = tid >> 5;
        s3[w][0] = es; s3[w][1] = sx; s3[w][2] = dt;
    }
    __syncthreads();
    if (tid == 0) {
        float E = 0.f, S = 0.f, D = 0.f;
        #pragma unroll
        for (int k = 0; k < 8; k++) { E += s3[k][0]; S += s3[k][1]; D += s3[k][2]; }
        const float lse = M + __logf(E);
        g_partials[i] = lse * g_rowS[t] - g_beta[t] * S + D - 0.8f * sb[1];
    }
}

// ---------------------------------------------------------------------------
// Deterministic two-stage reduction: 65536 -> 256 -> 1 (mean)
// ---------------------------------------------------------------------------
__global__ void reduce1_kernel() {
    const int tid = threadIdx.x;
    float v = g_partials[blockIdx.x * 256 + tid];
    v = warpSum(v);
    __shared__ float s[8];
    if ((tid & 31) == 0) s[tid >> 5] = v;
    __syncthreads();
    if (tid == 0) {
        float tot = 0.f;
        #pragma unroll
        for (int k = 0; k < 8; k++) tot += s[k];
        g_stage2[blockIdx.x] = tot;
    }
}

__global__ void reduce2_kernel(float* __restrict__ out, float invB) {
    const int tid = threadIdx.x;
    float v = g_stage2[tid];
    v = warpSum(v);
    __shared__ float s[8];
    if ((tid & 31) == 0) s[tid >> 5] = v;
    __syncthreads();
    if (tid == 0) {
        float tot = 0.f;
        #pragma unroll
        for (int k = 0; k < 8; k++) tot += s[k];
        out[0] = tot * invB;
    }
}

extern "C" void kernel_launch(void* const* d_in, const int* in_sizes, int n_in,
                              void* d_out, int out_size) {
    const float* x   = (const float*)d_in[0];
    const float* ca  = (const float*)d_in[1];
    const int*   tgt = (const int*)d_in[2];   // jnp.int64 w/o x64 => int32 on device
    float* out = (float*)d_out;

    const int B = in_sizes[2];          // 65536

    softmax_prep_kernel<<<C_CLASSES, 256>>>(ca);
    loss_kernel<<<B, 256>>>(x, tgt);
    reduce1_kernel<<<B / 256, 256>>>();
    reduce2_kernel<<<1, 256>>>(out, 1.0f / (float)B);
}

// round 5
// speedup vs baseline: 1.7372x; 1.7372x over previous
#include <cuda_runtime.h>
#include <cuda_bf16.h>

#define C_CLASSES 1000
#define NV4 250            // 1000 floats = 250 float4
#define SMOOTH 0.1f

// device scratch (no allocations allowed)
__device__ float g_A[C_CLASSES * C_CLASSES];   // pre-scaled: beta_t * A[t][j]
__device__ float g_beta[C_CLASSES];            // 0.1 / (1 - A[t][t])
__device__ float g_rowS[C_CLASSES];            // sum_j S[t][j]
__device__ float g_partials[65536];

__device__ __forceinline__ float warpMax(float v) {
    #pragma unroll
    for (int o = 16; o; o >>= 1) v = fmaxf(v, __shfl_xor_sync(0xffffffffu, v, o));
    return v;
}
__device__ __forceinline__ float warpSum(float v) {
    #pragma unroll
    for (int o = 16; o; o >>= 1) v += __shfl_xor_sync(0xffffffffu, v, o);
    return v;
}

// ---------------------------------------------------------------------------
// Kernel 1: row softmax of class_avg, fold beta scale into stored A.
// grid = 1000 blocks, 256 threads. Each thread owns one float4 (tid < 250).
// ---------------------------------------------------------------------------
__global__ void softmax_prep_kernel(const float* __restrict__ class_avg) {
    const int t   = blockIdx.x;
    const int tid = threadIdx.x;
    const bool full = (tid < NV4);

    const float4* row = (const float4*)(class_avg + (size_t)t * C_CLASSES);
    float4 v = make_float4(0.f, 0.f, 0.f, 0.f);
    if (full) v = row[tid];

    __shared__ float sred[8];
    __shared__ float sb[4];   // [0]=M, [1]=diag exp, [2]=scale

    float m = full ? fmaxf(fmaxf(v.x, v.y), fmaxf(v.z, v.w)) : -3.402823e38f;
    m = warpMax(m);
    if ((tid & 31) == 0) sred[tid >> 5] = m;
    __syncthreads();
    if (tid == 0) {
        float M = sred[0];
        #pragma unroll
        for (int k = 1; k < 8; k++) M = fmaxf(M, sred[k]);
        sb[0] = M;
    }
    __syncthreads();
    const float M = sb[0];

    float4 e = make_float4(0.f, 0.f, 0.f, 0.f);
    float s = 0.f;
    if (full) {
        e.x = __expf(v.x - M); e.y = __expf(v.y - M);
        e.z = __expf(v.z - M); e.w = __expf(v.w - M);
        s = (e.x + e.y) + (e.z + e.w);
    }
    s = warpSum(s);
    __syncthreads();
    if ((tid & 31) == 0) sred[tid >> 5] = s;
    if (tid == (t >> 2)) sb[1] = (&e.x)[t & 3];   // diag exp; t>>2 <= 249
    __syncthreads();
    if (tid == 0) {
        float S = 0.f;
        #pragma unroll
        for (int k = 0; k < 8; k++) S += sred[k];
        const float Att  = sb[1] / S;
        const float offm = 1.0f - Att;
        const float beta = SMOOTH / offm;
        g_beta[t] = beta;
        g_rowS[t] = (1.0f - SMOOTH) + SMOOTH * ((float)(C_CLASSES - 2) + Att) / offm;
        sb[2] = beta / S;
    }
    __syncthreads();
    const float sc = sb[2];
    if (full) {
        float4 o;
        o.x = e.x * sc; o.y = e.y * sc; o.z = e.z * sc; o.w = e.w * sc;
        ((float4*)(g_A + (size_t)t * C_CLASSES))[tid] = o;
    }
}

// ---------------------------------------------------------------------------
// Kernel 2: WARP-per-sample fused log-softmax dot. No block barriers.
// Each lane: 8 float4 of x (250 = 7*32 + 26) + 8 float4 of scaled A.
// loss_i = lse*rowS[t] - beta[t]*sum(x) + dot(Ascaled[t], x) - 0.8*x[t]
// ---------------------------------------------------------------------------
__global__ __launch_bounds__(256) void loss_kernel(const float* __restrict__ x,
                                                   const int* __restrict__ target) {
    const int i    = (blockIdx.x * blockDim.x + threadIdx.x) >> 5;  // row
    const int lane = threadIdx.x & 31;
    const int t    = __ldg(target + i);

    const float4* xr = (const float4*)(x   + (size_t)i * C_CLASSES);
    const float4* ar = (const float4*)(g_A + (size_t)t * C_CLASSES);
    const bool v7 = (lane < NV4 - 224);   // lane < 26

    // batch all 16 loads up front for max MLP
    float4 xv[8], av[8];
    #pragma unroll
    for (int k = 0; k < 7; k++) xv[k] = __ldcs(xr + lane + k * 32);
    xv[7] = v7 ? __ldcs(xr + lane + 224) : make_float4(0.f, 0.f, 0.f, 0.f);
    #pragma unroll
    for (int k = 0; k < 7; k++) av[k] = __ldg(ar + lane + k * 32);
    av[7] = v7 ? __ldg(ar + lane + 224) : make_float4(0.f, 0.f, 0.f, 0.f);

    // --- row max ---
    float m = -3.402823e38f;
    #pragma unroll
    for (int k = 0; k < 7; k++)
        m = fmaxf(m, fmaxf(fmaxf(xv[k].x, xv[k].y), fmaxf(xv[k].z, xv[k].w)));
    if (v7) m = fmaxf(m, fmaxf(fmaxf(xv[7].x, xv[7].y), fmaxf(xv[7].z, xv[7].w)));
    const float M = warpMax(m);

    // --- fused sums: exp-sum, plain sum, dot, target element ---
    const int tq = t >> 2, tc = t & 3;
    float es = 0.f, sx = 0.f, dt = 0.f, xt = 0.f;
    #pragma unroll
    for (int k = 0; k < 7; k++) {
        es += (__expf(xv[k].x - M) + __expf(xv[k].y - M)) +
              (__expf(xv[k].z - M) + __expf(xv[k].w - M));
        sx += (xv[k].x + xv[k].y) + (xv[k].z + xv[k].w);
        dt  = fmaf(xv[k].x, av[k].x, fmaf(xv[k].y, av[k].y,
              fmaf(xv[k].z, av[k].z, fmaf(xv[k].w, av[k].w, dt))));
        if (lane + k * 32 == tq)
            xt = (tc == 0) ? xv[k].x : (tc == 1) ? xv[k].y : (tc == 2) ? xv[k].z : xv[k].w;
    }
    if (v7) {
        es += (__expf(xv[7].x - M) + __expf(xv[7].y - M)) +
              (__expf(xv[7].z - M) + __expf(xv[7].w - M));
        sx += (xv[7].x + xv[7].y) + (xv[7].z + xv[7].w);
        dt  = fmaf(xv[7].x, av[7].x, fmaf(xv[7].y, av[7].y,
              fmaf(xv[7].z, av[7].z, fmaf(xv[7].w, av[7].w, dt))));
        if (lane + 224 == tq)
            xt = (tc == 0) ? xv[7].x : (tc == 1) ? xv[7].y : (tc == 2) ? xv[7].z : xv[7].w;
    }
    es = warpSum(es); sx = warpSum(sx); dt = warpSum(dt); xt = warpSum(xt);

    if (lane == 0) {
        const float lse = M + __logf(es);
        g_partials[i] = lse * __ldg(&g_rowS[t]) - __ldg(&g_beta[t]) * sx + dt - 0.8f * xt;
    }
}

// ---------------------------------------------------------------------------
// Single-kernel deterministic reduction: 65536 -> 1 (mean). 1 block, 1024 thr.
// ---------------------------------------------------------------------------
__global__ void reduce_kernel(float* __restrict__ out, float invB) {
    const int tid = threadIdx.x;
    const float4* p = (const float4*)g_partials;
    float s = 0.f;
    #pragma unroll
    for (int k = 0; k < 16; k++) {           // 16 * 1024 float4 = 65536 floats
        float4 v = p[tid + k * 1024];
        s += (v.x + v.y) + (v.z + v.w);
    }
    s = warpSum(s);
    __shared__ float sm[32];
    if ((tid & 31) == 0) sm[tid >> 5] = s;
    __syncthreads();
    if (tid < 32) {
        float v = sm[tid];
        v = warpSum(v);
        if (tid == 0) out[0] = v * invB;
    }
}

extern "C" void kernel_launch(void* const* d_in, const int* in_sizes, int n_in,
                              void* d_out, int out_size) {
    const float* x   = (const float*)d_in[0];
    const float* ca  = (const float*)d_in[1];
    const int*   tgt = (const int*)d_in[2];   // jnp.int64 w/o x64 => int32 on device
    float* out = (float*)d_out;

    const int B = in_sizes[2];                // 65536

    softmax_prep_kernel<<<C_CLASSES, 256>>>(ca);
    loss_kernel<<<B / 8, 256>>>(x, tgt);      // 8 warps/block, warp-per-row
    reduce_kernel<<<1, 1024>>>(out, 1.0f / (float)B);
}

// round 7
// speedup vs baseline: 2.0210x; 1.1634x over previous
#include <cuda_runtime.h>
#include <cuda_bf16.h>

#define C_CLASSES 1000
#define NV4 250            // 1000 floats = 250 float4
#define SMOOTH 0.1f

// device scratch (no allocations allowed)
__device__ __nv_bfloat16 g_Ab[C_CLASSES * C_CLASSES];  // pre-scaled beta_t*A[t][j], bf16
__device__ float g_beta[C_CLASSES];                    // 0.1 / (1 - A[t][t])
__device__ float g_rowS[C_CLASSES];                    // sum_j S[t][j]
__device__ float g_partials[65536];

__device__ __forceinline__ float warpMax(float v) {
    #pragma unroll
    for (int o = 16; o; o >>= 1) v = fmaxf(v, __shfl_xor_sync(0xffffffffu, v, o));
    return v;
}
__device__ __forceinline__ float warpSum(float v) {
    #pragma unroll
    for (int o = 16; o; o >>= 1) v += __shfl_xor_sync(0xffffffffu, v, o);
    return v;
}

// ---------------------------------------------------------------------------
// Kernel 1: WARP-per-row softmax of class_avg -> bf16 pre-scaled table.
// grid = 125 blocks x 256 thr = 1000 warps. No block barriers.
// ---------------------------------------------------------------------------
__global__ __launch_bounds__(256) void softmax_prep_kernel(const float* __restrict__ class_avg) {
    const int t    = (blockIdx.x * blockDim.x + threadIdx.x) >> 5;  // row 0..999
    const int lane = threadIdx.x & 31;
    const bool v7  = (lane < NV4 - 224);   // lane < 26

    const float4* row = (const float4*)(class_avg + (size_t)t * C_CLASSES);
    float4 v[8];
    #pragma unroll
    for (int k = 0; k < 7; k++) v[k] = __ldg(row + lane + k * 32);
    v[7] = v7 ? __ldg(row + lane + 224)
              : make_float4(-3.402823e38f, -3.402823e38f, -3.402823e38f, -3.402823e38f);

    // --- row max ---
    float m = -3.402823e38f;
    #pragma unroll
    for (int k = 0; k < 8; k++)
        m = fmaxf(m, fmaxf(fmaxf(v[k].x, v[k].y), fmaxf(v[k].z, v[k].w)));
    const float M = warpMax(m);

    // --- exp (in place), sum, diagonal extraction ---
    const int tq = t >> 2, tc = t & 3;
    float s = 0.f, diag = 0.f;
    #pragma unroll
    for (int k = 0; k < 8; k++) {
        v[k].x = __expf(v[k].x - M); v[k].y = __expf(v[k].y - M);
        v[k].z = __expf(v[k].z - M); v[k].w = __expf(v[k].w - M);
        s += (v[k].x + v[k].y) + (v[k].z + v[k].w);
        if (lane + k * 32 == tq)
            diag = (tc == 0) ? v[k].x : (tc == 1) ? v[k].y : (tc == 2) ? v[k].z : v[k].w;
    }
    const float S = warpSum(s);
    diag = warpSum(diag);              // broadcast diag exp to all lanes

    const float Att  = diag / S;
    const float offm = 1.0f - Att;
    const float beta = SMOOTH / offm;
    if (lane == 0) {
        g_beta[t] = beta;
        g_rowS[t] = (1.0f - SMOOTH) + SMOOTH * ((float)(C_CLASSES - 2) + Att) / offm;
    }
    const float sc = beta / S;

    // --- store pre-scaled row as bf16 (uint2 = 4 bf16, same index as float4) ---
    uint2* ab = (uint2*)(g_Ab + (size_t)t * C_CLASSES);
    #pragma unroll
    for (int k = 0; k < 7; k++) {
        __nv_bfloat162 lo = __float22bfloat162_rn(make_float2(v[k].x * sc, v[k].y * sc));
        __nv_bfloat162 hi = __float22bfloat162_rn(make_float2(v[k].z * sc, v[k].w * sc));
        uint2 o; o.x = *(unsigned*)&lo; o.y = *(unsigned*)&hi;
        ab[lane + k * 32] = o;
    }
    if (v7) {
        __nv_bfloat162 lo = __float22bfloat162_rn(make_float2(v[7].x * sc, v[7].y * sc));
        __nv_bfloat162 hi = __float22bfloat162_rn(make_float2(v[7].z * sc, v[7].w * sc));
        uint2 o; o.x = *(unsigned*)&lo; o.y = *(unsigned*)&hi;
        ab[lane + 224] = o;
    }
}

// ---------------------------------------------------------------------------
// Kernel 2: WARP-per-sample fused log-softmax dot. No block barriers.
// x: 8 float4/lane streamed (evict-first). A: 8 uint2/lane (bf16, L2-resident).
// loss_i = lse*rowS[t] - beta[t]*sum(x) + dot(Ascaled[t], x) - 0.8*x[t]
// ---------------------------------------------------------------------------
__global__ __launch_bounds__(256) void loss_kernel(const float* __restrict__ x,
                                                   const int* __restrict__ target) {
    const int i    = (blockIdx.x * blockDim.x + threadIdx.x) >> 5;  // row
    const int lane = threadIdx.x & 31;
    const int t    = __ldg(target + i);

    const float4* xr = (const float4*)(x + (size_t)i * C_CLASSES);
    const uint2*  ar = (const uint2*)(g_Ab + (size_t)t * C_CLASSES);
    const bool v7 = (lane < NV4 - 224);   // lane < 26

    // batch all loads up front for max MLP
    float4 xv[8]; uint2 av[8];
    #pragma unroll
    for (int k = 0; k < 7; k++) xv[k] = __ldcs(xr + lane + k * 32);
    xv[7] = v7 ? __ldcs(xr + lane + 224) : make_float4(0.f, 0.f, 0.f, 0.f);
    #pragma unroll
    for (int k = 0; k < 7; k++) av[k] = __ldg(ar + lane + k * 32);
    av[7] = v7 ? __ldg(ar + lane + 224) : make_uint2(0u, 0u);

    // --- row max ---
    float m = -3.402823e38f;
    #pragma unroll
    for (int k = 0; k < 7; k++)
        m = fmaxf(m, fmaxf(fmaxf(xv[k].x, xv[k].y), fmaxf(xv[k].z, xv[k].w)));
    if (v7) m = fmaxf(m, fmaxf(fmaxf(xv[7].x, xv[7].y), fmaxf(xv[7].z, xv[7].w)));
    const float M = warpMax(m);

    // --- fused sums: exp-sum, plain sum, dot(bf16 A), target element ---
    const int tq = t >> 2, tc = t & 3;
    float es = 0.f, sx = 0.f, dt = 0.f, xt = 0.f;
    #pragma unroll
    for (int k = 0; k < 8; k++) {
        if (k == 7 && !v7) break;
        es += (__expf(xv[k].x - M) + __expf(xv[k].y - M)) +
              (__expf(xv[k].z - M) + __expf(xv[k].w - M));
        sx += (xv[k].x + xv[k].y) + (xv[k].z + xv[k].w);
        const float2 a01 = __bfloat1622float2(*(const __nv_bfloat162*)&av[k].x);
        const float2 a23 = __bfloat1622float2(*(const __nv_bfloat162*)&av[k].y);
        dt = fmaf(xv[k].x, a01.x, fmaf(xv[k].y, a01.y,
             fmaf(xv[k].z, a23.x, fmaf(xv[k].w, a23.y, dt))));
        if (lane + k * 32 == tq)
            xt = (tc == 0) ? xv[k].x : (tc == 1) ? xv[k].y : (tc == 2) ? xv[k].z : xv[k].w;
    }
    es = warpSum(es); sx = warpSum(sx); dt = warpSum(dt); xt = warpSum(xt);

    if (lane == 0) {
        const float lse = M + __logf(es);
        g_partials[i] = lse * __ldg(&g_rowS[t]) - __ldg(&g_beta[t]) * sx + dt - 0.8f * xt;
    }
}

// ---------------------------------------------------------------------------
// Single-kernel deterministic reduction: 65536 -> 1 (mean). 1 block, 1024 thr.
// ---------------------------------------------------------------------------
__global__ void reduce_kernel(float* __restrict__ out, float invB) {
    const int tid = threadIdx.x;
    const float4* p = (const float4*)g_partials;
    float s = 0.f;
    #pragma unroll
    for (int k = 0; k < 16; k++) {           // 16 * 1024 float4 = 65536 floats
        float4 v = p[tid + k * 1024];
        s += (v.x + v.y) + (v.z + v.w);
    }
    s = warpSum(s);
    __shared__ float sm[32];
    if ((tid & 31) == 0) sm[tid >> 5] = s;
    __syncthreads();
    if (tid < 32) {
        float v = sm[tid];
        v = warpSum(v);
        if (tid == 0) out[0] = v * invB;
    }
}

extern "C" void kernel_launch(void* const* d_in, const int* in_sizes, int n_in,
                              void* d_out, int out_size) {
    const float* x   = (const float*)d_in[0];
    const float* ca  = (const float*)d_in[1];
    const int*   tgt = (const int*)d_in[2];   // jnp.int64 w/o x64 => int32 on device
    float* out = (float*)d_out;

    const int B = in_sizes[2];                // 65536

    softmax_prep_kernel<<<C_CLASSES / 8, 256>>>(ca);   // warp-per-row
    loss_kernel<<<B / 8, 256>>>(x, tgt);               // warp-per-row
    reduce_kernel<<<1, 1024>>>(out, 1.0f / (float)B);
}